// round 16
// baseline (speedup 1.0000x reference)
#include <cuda_runtime.h>
#include <cuda_fp16.h>
#include <math.h>

#define DIM 64
#define N_MAX 100000
#define E_MAX 1200000
#define T_MAX (E_MAX + N_MAX)
#define NSCAN_MAX 128
#define FLAG_RDY 0x40000000

// dynamic smem partition sizes (floats)
#define SW_ELEMS (64 * 72)
#define SX_ELEMS (128 * 68)
#define GEMM_SMEM_BYTES ((2 * SW_ELEMS + SX_ELEMS) * 4)

__device__ __half2 g_h16[N_MAX * 32];  // h = x @ W, fp16 (gather-only consumer)
__device__ float g_as[N_MAX];
__device__ float g_ad[N_MAX];
__device__ int   g_cnt[N_MAX];         // per-dst degree (zeroed by k_scan after use)
__device__ int   g_state[NSCAN_MAX];   // lookback state (zeroed by k_gemm blk 0)
__device__ int   g_off[N_MAX + 1];     // segment starts (+ total at [N])
__device__ int   g_cur[N_MAX];         // scatter cursor
__device__ int2  g_swE[T_MAX];         // dst-sorted (src, weight-bits)

// ---------------------------------------------------------------------------
// helpers: tf32 + packed f32x2
// ---------------------------------------------------------------------------
__device__ __forceinline__ float cvt_tf32(float x) {
    unsigned o;
    asm("cvt.rna.tf32.f32 %0, %1;" : "=r"(o) : "f"(x));
    return __uint_as_float(o);
}

__device__ __forceinline__ void mma_tf32(float c[4],
                                         unsigned a0, unsigned a1, unsigned a2, unsigned a3,
                                         unsigned b0, unsigned b1) {
    asm volatile(
        "mma.sync.aligned.m16n8k8.row.col.f32.tf32.tf32.f32 "
        "{%0,%1,%2,%3},{%4,%5,%6,%7},{%8,%9},{%0,%1,%2,%3};"
        : "+f"(c[0]), "+f"(c[1]), "+f"(c[2]), "+f"(c[3])
        : "r"(a0), "r"(a1), "r"(a2), "r"(a3), "r"(b0), "r"(b1));
}

__device__ __forceinline__ unsigned long long pk2(float x, float y) {
    unsigned long long r;
    asm("mov.b64 %0, {%1,%2};" : "=l"(r) : "f"(x), "f"(y));
    return r;
}
__device__ __forceinline__ void fma2(unsigned long long& c,
                                     unsigned long long a, unsigned long long b) {
    asm("fma.rn.f32x2 %0, %1, %2, %0;" : "+l"(c) : "l"(a), "l"(b));
}
__device__ __forceinline__ float2 upk2(unsigned long long v) {
    float x, y;
    asm("mov.b64 {%0,%1}, %2;" : "=f"(x), "=f"(y) : "l"(v));
    return make_float2(x, y);
}

// ---------------------------------------------------------------------------
// GEMM via 3xTF32 mma: h = x @ W (fp16 out), fused a_s/a_d dots, fused
// dst histogram, fused lookback-state zeroing. A staged via dynamic smem.
// ---------------------------------------------------------------------------
__global__ void k_gemm(const float* __restrict__ x, const float* __restrict__ W,
                       const float* __restrict__ att_src,
                       const float* __restrict__ att_dst,
                       const int* __restrict__ ei, int N, int E) {
    extern __shared__ float smem[];
    float* sWhi = smem;
    float* sWlo = smem + SW_ELEMS;
    float* sX   = smem + 2 * SW_ELEMS;   // stride 68

    int tid  = threadIdx.x;
    int w    = tid >> 5;
    int lane = tid & 31;
    int g    = lane >> 2;
    int tig  = lane & 3;
    int rb0  = blockIdx.x * 128;
    int row0 = rb0 + w * 16 + g;
    int row8 = row0 + 8;

    if (blockIdx.x == 0 && tid < NSCAN_MAX) g_state[tid] = 0;

    for (int i = tid; i < 64 * 64; i += 256) {
        int k = i >> 6, n = i & 63;
        float v  = W[i];
        float hi = cvt_tf32(v);
        sWhi[k * 72 + n] = hi;
        sWlo[k * 72 + n] = cvt_tf32(v - hi);
    }
    for (int i = tid; i < 128 * 16; i += 256) {
        int r = i >> 4, c4 = i & 15;
        float4 v = (rb0 + r < N) ? *(const float4*)&x[(rb0 + r) * 64 + c4 * 4]
                                 : make_float4(0.f, 0.f, 0.f, 0.f);
        *(float4*)&sX[r * 68 + c4 * 4] = v;
    }
    __syncthreads();

    int lr0 = w * 16 + g;
    int lr8 = lr0 + 8;
    float C[8][4] = {};

#pragma unroll
    for (int ks = 0; ks < 8; ks++) {
        int k0 = ks * 8;
        float a00 = sX[lr0 * 68 + k0 + tig];
        float a10 = sX[lr8 * 68 + k0 + tig];
        float a01 = sX[lr0 * 68 + k0 + tig + 4];
        float a11 = sX[lr8 * 68 + k0 + tig + 4];
        float h00 = cvt_tf32(a00), l00 = cvt_tf32(a00 - h00);
        float h10 = cvt_tf32(a10), l10 = cvt_tf32(a10 - h10);
        float h01 = cvt_tf32(a01), l01 = cvt_tf32(a01 - h01);
        float h11 = cvt_tf32(a11), l11 = cvt_tf32(a11 - h11);
        unsigned ah0 = __float_as_uint(h00), ah1 = __float_as_uint(h10);
        unsigned ah2 = __float_as_uint(h01), ah3 = __float_as_uint(h11);
        unsigned al0 = __float_as_uint(l00), al1 = __float_as_uint(l10);
        unsigned al2 = __float_as_uint(l01), al3 = __float_as_uint(l11);

#pragma unroll
        for (int nt = 0; nt < 8; nt++) {
            int n0 = nt * 8 + g;
            unsigned bh0 = __float_as_uint(sWhi[(k0 + tig)     * 72 + n0]);
            unsigned bh1 = __float_as_uint(sWhi[(k0 + tig + 4) * 72 + n0]);
            unsigned bl0 = __float_as_uint(sWlo[(k0 + tig)     * 72 + n0]);
            unsigned bl1 = __float_as_uint(sWlo[(k0 + tig + 4) * 72 + n0]);
            mma_tf32(C[nt], ah0, ah1, ah2, ah3, bh0, bh1);
            mma_tf32(C[nt], ah0, ah1, ah2, ah3, bl0, bl1);
            mma_tf32(C[nt], al0, al1, al2, al3, bh0, bh1);
        }
    }

    float ps0 = 0.f, ps8 = 0.f, pd0 = 0.f, pd8 = 0.f;
#pragma unroll
    for (int nt = 0; nt < 8; nt++) {
        int col0 = nt * 8 + tig * 2;
        float s0 = __ldg(&att_src[col0]), s1 = __ldg(&att_src[col0 + 1]);
        float d0 = __ldg(&att_dst[col0]), d1 = __ldg(&att_dst[col0 + 1]);
        ps0 += C[nt][0] * s0 + C[nt][1] * s1;
        pd0 += C[nt][0] * d0 + C[nt][1] * d1;
        ps8 += C[nt][2] * s0 + C[nt][3] * s1;
        pd8 += C[nt][2] * d0 + C[nt][3] * d1;
        if (row0 < N)
            g_h16[row0 * 32 + nt * 4 + tig] = __floats2half2_rn(C[nt][0], C[nt][1]);
        if (row8 < N)
            g_h16[row8 * 32 + nt * 4 + tig] = __floats2half2_rn(C[nt][2], C[nt][3]);
    }
#pragma unroll
    for (int o = 2; o; o >>= 1) {
        ps0 += __shfl_down_sync(0xffffffffu, ps0, o, 4);
        pd0 += __shfl_down_sync(0xffffffffu, pd0, o, 4);
        ps8 += __shfl_down_sync(0xffffffffu, ps8, o, 4);
        pd8 += __shfl_down_sync(0xffffffffu, pd8, o, 4);
    }
    if (tig == 0) {
        if (row0 < N) { g_as[row0] = ps0; g_ad[row0] = pd0; }
        if (row8 < N) { g_as[row8] = ps8; g_ad[row8] = pd8; }
    }

    int T = E + N;
    for (int i = blockIdx.x * 256 + tid; i < T; i += gridDim.x * 256) {
        int d = (i < E) ? __ldg(&ei[E + i]) : (i - E);
        atomicAdd(&g_cnt[d], 1);
    }
}

// ---------------------------------------------------------------------------
// Single-launch exclusive scan via aggregate lookback (98 co-resident blocks).
// ---------------------------------------------------------------------------
__device__ __forceinline__ int block_scan_1024(int v, int t, int* total) {
    int lane = t & 31, wid = t >> 5;
    int x = v;
#pragma unroll
    for (int o = 1; o < 32; o <<= 1) {
        int y = __shfl_up_sync(0xffffffffu, x, o);
        if (lane >= o) x += y;
    }
    __shared__ int ws[32];
    if (lane == 31) ws[wid] = x;
    __syncthreads();
    if (wid == 0) {
        int s = ws[lane];
#pragma unroll
        for (int o = 1; o < 32; o <<= 1) {
            int y = __shfl_up_sync(0xffffffffu, s, o);
            if (lane >= o) s += y;
        }
        ws[lane] = s;
    }
    __syncthreads();
    int add = wid ? ws[wid - 1] : 0;
    *total = ws[31];
    return x + add - v;
}

__global__ void k_scan(int n) {
    int t = threadIdx.x;
    int b = blockIdx.x;
    int i = b * 1024 + t;
    int v = (i < n) ? g_cnt[i] : 0;
    int total;
    int ex = block_scan_1024(v, t, &total);

    if (t == 0) atomicExch(&g_state[b], FLAG_RDY | total);

    __shared__ int s_prefix;
    if (t < 32) {
        int sum = 0;
        for (int base = 0; base < b; base += 32) {
            int p = base + t;
            if (p < b) {
                int val;
                do { val = *(volatile int*)&g_state[p]; } while (!(val & FLAG_RDY));
                sum += val & (FLAG_RDY - 1);
            }
        }
#pragma unroll
        for (int o = 16; o; o >>= 1) sum += __shfl_xor_sync(0xffffffffu, sum, o);
        if (t == 0) s_prefix = sum;
    }
    __syncthreads();

    int off = s_prefix + ex;
    if (i < n) {
        g_off[i] = off;
        g_cur[i] = off;
        g_cnt[i] = 0;
    }
    if (i == n - 1) g_off[n] = off + v;
}

// ---------------------------------------------------------------------------
// Scatter: w = exp(leaky_relu(a_s[s]+a_d[d])) into dst-sorted position.
// ---------------------------------------------------------------------------
__global__ void k_scatter(const int* __restrict__ ei, int N, int E) {
    int i = blockIdx.x * blockDim.x + threadIdx.x;
    if (i >= E + N) return;
    int s, d;
    if (i < E) { s = ei[i]; d = ei[E + i]; }
    else       { s = d = i - E; }
    float e = g_as[s] + g_ad[d];
    e = (e > 0.0f) ? e : 0.2f * e;
    float w = __expf(e);
    int pos = atomicAdd(&g_cur[d], 1);
    g_swE[pos] = make_int2(s, __float_as_int(w));
}

// ---------------------------------------------------------------------------
// Gather (fp16 h) + normalize + bias + LayerNorm. FULL WARP per node:
// lanes 0-15 process even edges, lanes 16-31 odd edges (identical control
// flow -> no divergence). 32-record windows staged to smem via ONE coalesced
// LDG; slack slots zero-filled. wsum: per-lane partial over staged slots,
// FULL-warp reduced at the end (all 32 slots).
// ---------------------------------------------------------------------------
__global__ void __launch_bounds__(256, 8)
k_gather(const float* __restrict__ bias,
         const float* __restrict__ gamma,
         const float* __restrict__ beta,
         float* __restrict__ out, int N) {
    __shared__ int2 sRec[8][32];   // [warp][slot]

    int wid  = threadIdx.x >> 5;
    int lane = threadIdx.x & 31;
    int sub  = lane & 15;          // dim group: dims [sub*4, sub*4+4)
    int half = lane >> 4;          // 0: even edges, 1: odd edges
    int node = blockIdx.x * 8 + wid;
    if (node >= N) return;

    int start = g_off[node];
    int deg   = g_off[node + 1] - start;

    unsigned long long acc01 = 0ull, acc23 = 0ull;
    float wsum = 0.0f;

    for (int base = 0; base < deg; base += 32) {
        int2 rec = make_int2(0, 0);    // zero weight -> harmless slack
        if (base + lane < deg) rec = __ldg(&g_swE[start + base + lane]);
        wsum += __int_as_float(rec.y);   // per-lane partial (each record once)
        sRec[wid][lane] = rec;
        __syncwarp();

        int m     = min(32, deg - base);
        int iters = (m + 1) >> 1;        // edge-pairs in this window
        int j = 0;
        for (; j + 2 <= iters; j += 2) {
            int2 e0 = sRec[wid][2 * j + half];
            int2 e1 = sRec[wid][2 * j + 2 + half];
            uint2 r0 = *(const uint2*)&g_h16[e0.x * 32 + sub * 2];
            uint2 r1 = *(const uint2*)&g_h16[e1.x * 32 + sub * 2];
            float2 a0 = __half22float2(*(__half2*)&r0.x);
            float2 b0 = __half22float2(*(__half2*)&r0.y);
            float2 a1 = __half22float2(*(__half2*)&r1.x);
            float2 b1 = __half22float2(*(__half2*)&r1.y);
            unsigned long long w0p = pk2(__int_as_float(e0.y), __int_as_float(e0.y));
            unsigned long long w1p = pk2(__int_as_float(e1.y), __int_as_float(e1.y));
            fma2(acc01, pk2(a0.x, a0.y), w0p);
            fma2(acc23, pk2(b0.x, b0.y), w0p);
            fma2(acc01, pk2(a1.x, a1.y), w1p);
            fma2(acc23, pk2(b1.x, b1.y), w1p);
        }
        if (j < iters) {
            int2 e0 = sRec[wid][2 * j + half];
            uint2 r0 = *(const uint2*)&g_h16[e0.x * 32 + sub * 2];
            float2 a0 = __half22float2(*(__half2*)&r0.x);
            float2 b0 = __half22float2(*(__half2*)&r0.y);
            unsigned long long w0p = pk2(__int_as_float(e0.y), __int_as_float(e0.y));
            fma2(acc01, pk2(a0.x, a0.y), w0p);
            fma2(acc23, pk2(b0.x, b0.y), w0p);
        }
        __syncwarp();   // before next window overwrites sRec
    }

    // combine halves (lane L and L^16 hold partial sums for the same dims)
    float2 v01 = upk2(acc01);
    float2 v23 = upk2(acc23);
    float a0 = v01.x, a1 = v01.y, a2 = v23.x, a3 = v23.y;
    a0 += __shfl_xor_sync(0xffffffffu, a0, 16);
    a1 += __shfl_xor_sync(0xffffffffu, a1, 16);
    a2 += __shfl_xor_sync(0xffffffffu, a2, 16);
    a3 += __shfl_xor_sync(0xffffffffu, a3, 16);
    // wsum partials span ALL 32 slots -> full-warp reduction
#pragma unroll
    for (int o = 16; o; o >>= 1) wsum += __shfl_xor_sync(0xffffffffu, wsum, o);

    float inv = 1.0f / wsum;
    float4 bv = *(const float4*)&bias[sub * 4];
    float v0 = a0 * inv + bv.x;
    float v1 = a1 * inv + bv.y;
    float v2 = a2 * inv + bv.z;
    float v3 = a3 * inv + bv.w;

    float sum = v0 + v1 + v2 + v3;
#pragma unroll
    for (int o = 8; o; o >>= 1) sum += __shfl_xor_sync(0xffffffffu, sum, o, 16);
    float mu = sum * (1.0f / 64.0f);

    float d0 = v0 - mu, d1 = v1 - mu, d2 = v2 - mu, d3 = v3 - mu;
    float sq = d0*d0 + d1*d1 + d2*d2 + d3*d3;
#pragma unroll
    for (int o = 8; o; o >>= 1) sq += __shfl_xor_sync(0xffffffffu, sq, o, 16);
    float rs = rsqrtf(sq * (1.0f / 64.0f) + 1e-5f);

    if (half == 0) {
        float4 gv = *(const float4*)&gamma[sub * 4];
        float4 be = *(const float4*)&beta[sub * 4];
        float4 o4;
        o4.x = d0 * rs * gv.x + be.x;
        o4.y = d1 * rs * gv.y + be.y;
        o4.z = d2 * rs * gv.z + be.z;
        o4.w = d3 * rs * gv.w + be.w;
        *(float4*)&out[node * 64 + sub * 4] = o4;
    }
}

// ---------------------------------------------------------------------------
extern "C" void kernel_launch(void* const* d_in, const int* in_sizes, int n_in,
                              void* d_out, int out_size) {
    const float* x       = (const float*)d_in[0];
    const int*   ei      = (const int*)d_in[1];     // int32
    const float* W       = (const float*)d_in[2];
    const float* att_src = (const float*)d_in[3];
    const float* att_dst = (const float*)d_in[4];
    const float* bias    = (const float*)d_in[5];
    const float* gamma   = (const float*)d_in[6];
    const float* beta    = (const float*)d_in[7];
    float*       out     = (float*)d_out;

    int N = in_sizes[0] / DIM;
    int E = in_sizes[1] / 2;
    int T = E + N;
    int nScanBlocks = (N + 1023) / 1024;

    cudaFuncSetAttribute(k_gemm, cudaFuncAttributeMaxDynamicSharedMemorySize,
                         GEMM_SMEM_BYTES);

    k_gemm   <<<(N + 127) / 128, 256, GEMM_SMEM_BYTES>>>(x, W, att_src, att_dst, ei, N, E);
    k_scan   <<<nScanBlocks, 1024>>>(N);
    k_scatter<<<(T + 255) / 256, 256>>>(ei, N, E);
    k_gather <<<(N + 7) / 8, 256>>>(bias, gamma, beta, out, N);
}

// round 17
// speedup vs baseline: 1.1367x; 1.1367x over previous
#include <cuda_runtime.h>
#include <cuda_fp16.h>
#include <math.h>

#define DIM 64
#define N_MAX 100000
#define E_MAX 1200000
#define T_MAX (E_MAX + N_MAX)
#define NSCAN_MAX 128
#define FLAG_RDY 0x40000000

// dynamic smem partition sizes (floats)
#define SW_ELEMS (64 * 72)
#define SX_ELEMS (128 * 68)
#define GEMM_SMEM_BYTES ((2 * SW_ELEMS + SX_ELEMS) * 4)

__device__ __half2 g_h16[N_MAX * 32];  // h = x @ W, fp16 (gather-only consumer)
__device__ float g_as[N_MAX];
__device__ float g_ad[N_MAX];
__device__ int   g_cnt[N_MAX];         // per-dst degree (zeroed by k_scan after use)
__device__ int   g_state[NSCAN_MAX];   // lookback state (zeroed by k_gemm blk 0)
__device__ int   g_off[N_MAX + 1];     // segment starts (+ total at [N])
__device__ int   g_cur[N_MAX];         // scatter cursor
__device__ int2  g_swE[T_MAX];         // dst-sorted (src, weight-bits)

// ---------------------------------------------------------------------------
// helpers: tf32 + packed f32x2
// ---------------------------------------------------------------------------
__device__ __forceinline__ float cvt_tf32(float x) {
    unsigned o;
    asm("cvt.rna.tf32.f32 %0, %1;" : "=r"(o) : "f"(x));
    return __uint_as_float(o);
}

__device__ __forceinline__ void mma_tf32(float c[4],
                                         unsigned a0, unsigned a1, unsigned a2, unsigned a3,
                                         unsigned b0, unsigned b1) {
    asm volatile(
        "mma.sync.aligned.m16n8k8.row.col.f32.tf32.tf32.f32 "
        "{%0,%1,%2,%3},{%4,%5,%6,%7},{%8,%9},{%0,%1,%2,%3};"
        : "+f"(c[0]), "+f"(c[1]), "+f"(c[2]), "+f"(c[3])
        : "r"(a0), "r"(a1), "r"(a2), "r"(a3), "r"(b0), "r"(b1));
}

__device__ __forceinline__ unsigned long long pk2(float x, float y) {
    unsigned long long r;
    asm("mov.b64 %0, {%1,%2};" : "=l"(r) : "f"(x), "f"(y));
    return r;
}
__device__ __forceinline__ void fma2(unsigned long long& c,
                                     unsigned long long a, unsigned long long b) {
    asm("fma.rn.f32x2 %0, %1, %2, %0;" : "+l"(c) : "l"(a), "l"(b));
}
__device__ __forceinline__ float2 upk2(unsigned long long v) {
    float x, y;
    asm("mov.b64 {%0,%1}, %2;" : "=f"(x), "=f"(y) : "l"(v));
    return make_float2(x, y);
}

// ---------------------------------------------------------------------------
// GEMM via 2xTF32 mma (A tf32-rounded, B hi+lo): h = x @ W (fp16 out),
// fused a_s/a_d dots, fused dst histogram, fused lookback-state zeroing.
// ---------------------------------------------------------------------------
__global__ void k_gemm(const float* __restrict__ x, const float* __restrict__ W,
                       const float* __restrict__ att_src,
                       const float* __restrict__ att_dst,
                       const int* __restrict__ ei, int N, int E) {
    extern __shared__ float smem[];
    float* sWhi = smem;
    float* sWlo = smem + SW_ELEMS;
    float* sX   = smem + 2 * SW_ELEMS;   // stride 68

    int tid  = threadIdx.x;
    int w    = tid >> 5;
    int lane = tid & 31;
    int g    = lane >> 2;
    int tig  = lane & 3;
    int rb0  = blockIdx.x * 128;
    int row0 = rb0 + w * 16 + g;
    int row8 = row0 + 8;

    if (blockIdx.x == 0 && tid < NSCAN_MAX) g_state[tid] = 0;

    for (int i = tid; i < 64 * 64; i += 256) {
        int k = i >> 6, n = i & 63;
        float v  = W[i];
        float hi = cvt_tf32(v);
        sWhi[k * 72 + n] = hi;
        sWlo[k * 72 + n] = cvt_tf32(v - hi);
    }
    for (int i = tid; i < 128 * 16; i += 256) {
        int r = i >> 4, c4 = i & 15;
        float4 v = (rb0 + r < N) ? *(const float4*)&x[(rb0 + r) * 64 + c4 * 4]
                                 : make_float4(0.f, 0.f, 0.f, 0.f);
        *(float4*)&sX[r * 68 + c4 * 4] = v;
    }
    __syncthreads();

    int lr0 = w * 16 + g;
    int lr8 = lr0 + 8;
    float C[8][4] = {};

#pragma unroll
    for (int ks = 0; ks < 8; ks++) {
        int k0 = ks * 8;
        // A fragment tf32-rounded only (low-order term dropped: h is stored
        // fp16 downstream, which dominates the residual anyway)
        unsigned ah0 = __float_as_uint(cvt_tf32(sX[lr0 * 68 + k0 + tig]));
        unsigned ah1 = __float_as_uint(cvt_tf32(sX[lr8 * 68 + k0 + tig]));
        unsigned ah2 = __float_as_uint(cvt_tf32(sX[lr0 * 68 + k0 + tig + 4]));
        unsigned ah3 = __float_as_uint(cvt_tf32(sX[lr8 * 68 + k0 + tig + 4]));

#pragma unroll
        for (int nt = 0; nt < 8; nt++) {
            int n0 = nt * 8 + g;
            unsigned bh0 = __float_as_uint(sWhi[(k0 + tig)     * 72 + n0]);
            unsigned bh1 = __float_as_uint(sWhi[(k0 + tig + 4) * 72 + n0]);
            unsigned bl0 = __float_as_uint(sWlo[(k0 + tig)     * 72 + n0]);
            unsigned bl1 = __float_as_uint(sWlo[(k0 + tig + 4) * 72 + n0]);
            mma_tf32(C[nt], ah0, ah1, ah2, ah3, bh0, bh1);
            mma_tf32(C[nt], ah0, ah1, ah2, ah3, bl0, bl1);
        }
    }

    float ps0 = 0.f, ps8 = 0.f, pd0 = 0.f, pd8 = 0.f;
#pragma unroll
    for (int nt = 0; nt < 8; nt++) {
        int col0 = nt * 8 + tig * 2;
        float s0 = __ldg(&att_src[col0]), s1 = __ldg(&att_src[col0 + 1]);
        float d0 = __ldg(&att_dst[col0]), d1 = __ldg(&att_dst[col0 + 1]);
        ps0 += C[nt][0] * s0 + C[nt][1] * s1;
        pd0 += C[nt][0] * d0 + C[nt][1] * d1;
        ps8 += C[nt][2] * s0 + C[nt][3] * s1;
        pd8 += C[nt][2] * d0 + C[nt][3] * d1;
        if (row0 < N)
            g_h16[row0 * 32 + nt * 4 + tig] = __floats2half2_rn(C[nt][0], C[nt][1]);
        if (row8 < N)
            g_h16[row8 * 32 + nt * 4 + tig] = __floats2half2_rn(C[nt][2], C[nt][3]);
    }
#pragma unroll
    for (int o = 2; o; o >>= 1) {
        ps0 += __shfl_down_sync(0xffffffffu, ps0, o, 4);
        pd0 += __shfl_down_sync(0xffffffffu, pd0, o, 4);
        ps8 += __shfl_down_sync(0xffffffffu, ps8, o, 4);
        pd8 += __shfl_down_sync(0xffffffffu, pd8, o, 4);
    }
    if (tig == 0) {
        if (row0 < N) { g_as[row0] = ps0; g_ad[row0] = pd0; }
        if (row8 < N) { g_as[row8] = ps8; g_ad[row8] = pd8; }
    }

    int T = E + N;
    for (int i = blockIdx.x * 256 + tid; i < T; i += gridDim.x * 256) {
        int d = (i < E) ? __ldg(&ei[E + i]) : (i - E);
        atomicAdd(&g_cnt[d], 1);
    }
}

// ---------------------------------------------------------------------------
// Single-launch exclusive scan via aggregate lookback (98 co-resident blocks).
// ---------------------------------------------------------------------------
__device__ __forceinline__ int block_scan_1024(int v, int t, int* total) {
    int lane = t & 31, wid = t >> 5;
    int x = v;
#pragma unroll
    for (int o = 1; o < 32; o <<= 1) {
        int y = __shfl_up_sync(0xffffffffu, x, o);
        if (lane >= o) x += y;
    }
    __shared__ int ws[32];
    if (lane == 31) ws[wid] = x;
    __syncthreads();
    if (wid == 0) {
        int s = ws[lane];
#pragma unroll
        for (int o = 1; o < 32; o <<= 1) {
            int y = __shfl_up_sync(0xffffffffu, s, o);
            if (lane >= o) s += y;
        }
        ws[lane] = s;
    }
    __syncthreads();
    int add = wid ? ws[wid - 1] : 0;
    *total = ws[31];
    return x + add - v;
}

__global__ void k_scan(int n) {
    int t = threadIdx.x;
    int b = blockIdx.x;
    int i = b * 1024 + t;
    int v = (i < n) ? g_cnt[i] : 0;
    int total;
    int ex = block_scan_1024(v, t, &total);

    if (t == 0) atomicExch(&g_state[b], FLAG_RDY | total);

    __shared__ int s_prefix;
    if (t < 32) {
        int sum = 0;
        for (int base = 0; base < b; base += 32) {
            int p = base + t;
            if (p < b) {
                int val;
                do { val = *(volatile int*)&g_state[p]; } while (!(val & FLAG_RDY));
                sum += val & (FLAG_RDY - 1);
            }
        }
#pragma unroll
        for (int o = 16; o; o >>= 1) sum += __shfl_xor_sync(0xffffffffu, sum, o);
        if (t == 0) s_prefix = sum;
    }
    __syncthreads();

    int off = s_prefix + ex;
    if (i < n) {
        g_off[i] = off;
        g_cur[i] = off;
        g_cnt[i] = 0;
    }
    if (i == n - 1) g_off[n] = off + v;
}

// ---------------------------------------------------------------------------
// Scatter: w = exp(leaky_relu(a_s[s]+a_d[d])) into dst-sorted position.
// ---------------------------------------------------------------------------
__global__ void k_scatter(const int* __restrict__ ei, int N, int E) {
    int i = blockIdx.x * blockDim.x + threadIdx.x;
    if (i >= E + N) return;
    int s, d;
    if (i < E) { s = ei[i]; d = ei[E + i]; }
    else       { s = d = i - E; }
    float e = g_as[s] + g_ad[d];
    e = (e > 0.0f) ? e : 0.2f * e;
    float w = __expf(e);
    int pos = atomicAdd(&g_cur[d], 1);
    g_swE[pos] = make_int2(s, __float_as_int(w));
}

// ---------------------------------------------------------------------------
// Gather (fp16 h) + normalize + bias + LayerNorm. Half-warp (16 lanes) per
// node (best measured variant: R14). Records staged per 16-edge window via
// ONE coalesced LDG -> smem, inner loop reads via broadcast LDS; per-window
// wsum reduction; 2-edge unroll.
// ---------------------------------------------------------------------------
__global__ void __launch_bounds__(256, 8)
k_gather(const float* __restrict__ bias,
         const float* __restrict__ gamma,
         const float* __restrict__ beta,
         float* __restrict__ out, int N) {
    __shared__ int2 sRec[16][16];   // [half-warp][slot]

    int idx  = blockIdx.x * 256 + threadIdx.x;
    int node = idx >> 4;
    int sub  = idx & 15;
    int hw   = threadIdx.x >> 4;                  // half-warp id in block
    unsigned hm = 0xFFFFu << (threadIdx.x & 16);  // half-warp mask
    if (node >= N) return;

    int start = g_off[node];
    int deg   = g_off[node + 1] - start;

    unsigned long long acc01 = 0ull, acc23 = 0ull;
    float wsum = 0.0f;

    for (int base = 0; base < deg; base += 16) {
        int m = min(16, deg - base);
        int2 rec = make_int2(0, 0);
        if (base + sub < deg) rec = __ldg(&g_swE[start + base + sub]);

        // window weight-sum (lanes beyond m hold w=0)
        float ws = __int_as_float(rec.y);
#pragma unroll
        for (int o = 8; o; o >>= 1) ws += __shfl_xor_sync(hm, ws, o, 16);
        wsum += ws;

        sRec[hw][sub] = rec;
        __syncwarp(hm);

        int j = 0;
        for (; j + 2 <= m; j += 2) {
            int2 e0 = sRec[hw][j];
            int2 e1 = sRec[hw][j + 1];
            uint2 r0 = *(const uint2*)&g_h16[e0.x * 32 + sub * 2];
            uint2 r1 = *(const uint2*)&g_h16[e1.x * 32 + sub * 2];
            float2 a0 = __half22float2(*(__half2*)&r0.x);
            float2 b0 = __half22float2(*(__half2*)&r0.y);
            float2 a1 = __half22float2(*(__half2*)&r1.x);
            float2 b1 = __half22float2(*(__half2*)&r1.y);
            unsigned long long w0p = pk2(__int_as_float(e0.y), __int_as_float(e0.y));
            unsigned long long w1p = pk2(__int_as_float(e1.y), __int_as_float(e1.y));
            fma2(acc01, pk2(a0.x, a0.y), w0p);
            fma2(acc23, pk2(b0.x, b0.y), w0p);
            fma2(acc01, pk2(a1.x, a1.y), w1p);
            fma2(acc23, pk2(b1.x, b1.y), w1p);
        }
        if (j < m) {
            int2 e0 = sRec[hw][j];
            uint2 r0 = *(const uint2*)&g_h16[e0.x * 32 + sub * 2];
            float2 a0 = __half22float2(*(__half2*)&r0.x);
            float2 b0 = __half22float2(*(__half2*)&r0.y);
            unsigned long long w0p = pk2(__int_as_float(e0.y), __int_as_float(e0.y));
            fma2(acc01, pk2(a0.x, a0.y), w0p);
            fma2(acc23, pk2(b0.x, b0.y), w0p);
        }
        __syncwarp(hm);   // before next window overwrites sRec
    }

    float2 v01 = upk2(acc01);
    float2 v23 = upk2(acc23);

    float inv = 1.0f / wsum;
    float4 bv = *(const float4*)&bias[sub * 4];
    float v0 = v01.x * inv + bv.x;
    float v1 = v01.y * inv + bv.y;
    float v2 = v23.x * inv + bv.z;
    float v3 = v23.y * inv + bv.w;

    float sum = v0 + v1 + v2 + v3;
#pragma unroll
    for (int o = 8; o; o >>= 1) sum += __shfl_xor_sync(hm, sum, o, 16);
    float mu = sum * (1.0f / 64.0f);

    float d0 = v0 - mu, d1 = v1 - mu, d2 = v2 - mu, d3 = v3 - mu;
    float sq = d0*d0 + d1*d1 + d2*d2 + d3*d3;
#pragma unroll
    for (int o = 8; o; o >>= 1) sq += __shfl_xor_sync(hm, sq, o, 16);
    float rs = rsqrtf(sq * (1.0f / 64.0f) + 1e-5f);

    float4 gv = *(const float4*)&gamma[sub * 4];
    float4 be = *(const float4*)&beta[sub * 4];
    float4 o4;
    o4.x = d0 * rs * gv.x + be.x;
    o4.y = d1 * rs * gv.y + be.y;
    o4.z = d2 * rs * gv.z + be.z;
    o4.w = d3 * rs * gv.w + be.w;
    *(float4*)&out[node * 64 + sub * 4] = o4;
}

// ---------------------------------------------------------------------------
extern "C" void kernel_launch(void* const* d_in, const int* in_sizes, int n_in,
                              void* d_out, int out_size) {
    const float* x       = (const float*)d_in[0];
    const int*   ei      = (const int*)d_in[1];     // int32
    const float* W       = (const float*)d_in[2];
    const float* att_src = (const float*)d_in[3];
    const float* att_dst = (const float*)d_in[4];
    const float* bias    = (const float*)d_in[5];
    const float* gamma   = (const float*)d_in[6];
    const float* beta    = (const float*)d_in[7];
    float*       out     = (float*)d_out;

    int N = in_sizes[0] / DIM;
    int E = in_sizes[1] / 2;
    int T = E + N;
    int nScanBlocks = (N + 1023) / 1024;

    cudaFuncSetAttribute(k_gemm, cudaFuncAttributeMaxDynamicSharedMemorySize,
                         GEMM_SMEM_BYTES);

    k_gemm   <<<(N + 127) / 128, 256, GEMM_SMEM_BYTES>>>(x, W, att_src, att_dst, ei, N, E);
    k_scan   <<<nScanBlocks, 1024>>>(N);
    k_scatter<<<(T + 255) / 256, 256>>>(ei, N, E);
    k_gather <<<(N * 16 + 255) / 256, 256>>>(bias, gamma, beta, out, N);
}